// round 9
// baseline (speedup 1.0000x reference)
#include <cuda_runtime.h>
#include <math_constants.h>

// Problem constants (fixed: centers [8, 4096, 3] fp32)
#define BATCH    8
#define NPTS     4096
#define TOTPTS   (BATCH * NPTS)       // 32768
#define TPB      128                  // threads per block (min kernel)
#define IPT      4                    // i-points per thread
#define ITILE    (TPB * IPT)          // 512 i per block
#define NITILES  (NPTS / ITILE)       // 8
#define SSPLIT   64                   // j-splits
#define JT       (NPTS / SSPLIT)      // 64 j per block
#define NBLK_MIN (BATCH * NITILES * SSPLIT)   // 4096
#define CMB_BLKS 256
#define CMB_TPB  128
#define TARGET_F 0.2f

// Scratch (static device globals — no allocation allowed)
// Partial mins in [split][point] layout: coalesced store AND load. 8 MB.
__device__ float g_pmin[SSPLIT * TOTPTS];
__device__ float g_partials[CMB_BLKS];
__device__ unsigned int g_sync;   // zero-initialized; self-resets each call

// ---- packed f32x2 helpers (FFMA2: only reachable via PTX) ----
__device__ __forceinline__ unsigned long long pack2(float a, float b) {
    unsigned long long r;
    asm("mov.b64 %0, {%1, %2};" : "=l"(r) : "f"(a), "f"(b));
    return r;
}
__device__ __forceinline__ unsigned long long fma2(unsigned long long a,
                                                   unsigned long long b,
                                                   unsigned long long c) {
    unsigned long long d;
    asm("fma.rn.f32x2 %0, %1, %2, %3;" : "=l"(d) : "l"(a), "l"(b), "l"(c));
    return d;
}
__device__ __forceinline__ float2 unpack2(unsigned long long v) {
    float2 f;
    asm("mov.b64 {%0, %1}, %2;" : "=f"(f.x), "=f"(f.y) : "l"(v));
    return f;
}

__global__ void __launch_bounds__(TPB)
nn_min_kernel(const float* __restrict__ centers)
{
    // SoA j-tile: LDS.128 per array yields pre-packed {j,j+1} f32x2 lanes
    __shared__ __align__(16) float spx[JT], spy[JT], spz[JT], spw[JT];

    const int blk = blockIdx.x;
    const int s   = blk & (SSPLIT - 1);            // j-split
    const int it  = (blk >> 6) & (NITILES - 1);    // i-tile
    const int b   = blk >> 9;                      // batch
    const int tid = threadIdx.x;

    const float* cb = centers + (size_t)b * NPTS * 3;
    const int j_lo  = s  * JT;
    const int i_lo  = it * ITILE;

    // Stage j-tile (64 points; threads >= JT idle here)
    for (int p = tid; p < JT; p += TPB) {
        float x = cb[3 * (j_lo + p) + 0];
        float y = cb[3 * (j_lo + p) + 1];
        float z = cb[3 * (j_lo + p) + 2];
        spx[p] = x; spy[p] = y; spz[p] = z;
        spw[p] = fmaf(x, x, fmaf(y, y, z * z));
    }

    // i-constants, pre-packed {c,c} once
    unsigned long long ax2[IPT], ay2[IPT], az2[IPT];
    float sqi[IPT], tminA[IPT], tminB[IPT];
    int   msel[IPT];   // local j index equal to this i (may be out of range)
    #pragma unroll
    for (int k = 0; k < IPT; ++k) {
        const int gi = i_lo + tid + k * TPB;
        float x = cb[3 * gi + 0];
        float y = cb[3 * gi + 1];
        float z = cb[3 * gi + 2];
        ax2[k] = pack2(-2.0f * x, -2.0f * x);
        ay2[k] = pack2(-2.0f * y, -2.0f * y);
        az2[k] = pack2(-2.0f * z, -2.0f * z);
        sqi[k] = fmaf(x, x, fmaf(y, y, z * z));
        tminA[k] = CUDART_INF_F;
        tminB[k] = CUDART_INF_F;
        msel[k] = gi - j_lo;
    }
    __syncthreads();

    const ulonglong2* px2 = (const ulonglong2*)spx;
    const ulonglong2* py2 = (const ulonglong2*)spy;
    const ulonglong2* pz2 = (const ulonglong2*)spz;
    const ulonglong2* pw2 = (const ulonglong2*)spw;

    if ((s >> 3) != it) {
        // Off-diagonal block: clean fully-unrolled loop, no compares
        #pragma unroll
        for (int q = 0; q < JT / 4; ++q) {
            const ulonglong2 px = px2[q], py = py2[q], pz = pz2[q], pw = pw2[q];
            #pragma unroll
            for (int k = 0; k < IPT; ++k) {
                unsigned long long t0 = fma2(pz.x, az2[k], pw.x);
                t0 = fma2(py.x, ay2[k], t0);
                t0 = fma2(px.x, ax2[k], t0);
                unsigned long long t1 = fma2(pz.y, az2[k], pw.y);
                t1 = fma2(py.y, ay2[k], t1);
                t1 = fma2(px.y, ax2[k], t1);
                float2 a = unpack2(t0), c = unpack2(t1);
                tminA[k] = fminf(tminA[k], fminf(a.x, a.y));
                tminB[k] = fminf(tminB[k], fminf(c.x, c.y));
            }
        }
    } else {
        // Diagonal block (1/8 of blocks): predicate out j == i
        #pragma unroll
        for (int q = 0; q < JT / 4; ++q) {
            const int jb = q * 4;
            const ulonglong2 px = px2[q], py = py2[q], pz = pz2[q], pw = pw2[q];
            #pragma unroll
            for (int k = 0; k < IPT; ++k) {
                unsigned long long t0 = fma2(pz.x, az2[k], pw.x);
                t0 = fma2(py.x, ay2[k], t0);
                t0 = fma2(px.x, ax2[k], t0);
                unsigned long long t1 = fma2(pz.y, az2[k], pw.y);
                t1 = fma2(py.y, ay2[k], t1);
                t1 = fma2(px.y, ax2[k], t1);
                float2 a = unpack2(t0), c = unpack2(t1);
                const int m = msel[k];
                a.x = (jb + 0 == m) ? CUDART_INF_F : a.x;
                a.y = (jb + 1 == m) ? CUDART_INF_F : a.y;
                c.x = (jb + 2 == m) ? CUDART_INF_F : c.x;
                c.y = (jb + 3 == m) ? CUDART_INF_F : c.y;
                tminA[k] = fminf(tminA[k], fminf(a.x, a.y));
                tminB[k] = fminf(tminB[k], fminf(c.x, c.y));
            }
        }
    }

    // Coalesced partial store: pm[s][point]
    float* pm = g_pmin + (size_t)s * TOTPTS + b * NPTS + i_lo + tid;
    #pragma unroll
    for (int k = 0; k < IPT; ++k)
        pm[k * TPB] = sqi[k] + fminf(tminA[k], tminB[k]);
}

// Combine partial mins -> per-point loss -> global mean.
// One point per thread, 64 independent coalesced loads (MLP=64), all SMs busy.
// Fused final via last-block-done; deterministic fixed-order sums.
__global__ void __launch_bounds__(CMB_TPB)
nn_combine_final(float* __restrict__ out)
{
    __shared__ float red[CMB_TPB];
    const int tid = threadIdx.x;
    const int pt  = blockIdx.x * CMB_TPB + tid;    // point index 0..32767

    float m0 = CUDART_INF_F, m1 = CUDART_INF_F;
    float m2 = CUDART_INF_F, m3 = CUDART_INF_F;
    #pragma unroll
    for (int s = 0; s < SSPLIT; s += 4) {
        m0 = fminf(m0, g_pmin[(size_t)(s + 0) * TOTPTS + pt]);
        m1 = fminf(m1, g_pmin[(size_t)(s + 1) * TOTPTS + pt]);
        m2 = fminf(m2, g_pmin[(size_t)(s + 2) * TOTPTS + pt]);
        m3 = fminf(m3, g_pmin[(size_t)(s + 3) * TOTPTS + pt]);
    }
    float m = fminf(fminf(m0, m1), fminf(m2, m3));
    float diff = sqrtf(fmaxf(m, 0.0f)) - TARGET_F;   // clamp like reference
    red[tid] = diff * diff;
    __syncthreads();
    #pragma unroll
    for (int st = CMB_TPB / 2; st > 0; st >>= 1) {
        if (tid < st) red[tid] += red[tid + st];
        __syncthreads();
    }
    if (tid == 0) {
        g_partials[blockIdx.x] = red[0];
        __threadfence();
        if (atomicAdd(&g_sync, 1u) == CMB_BLKS - 1) {
            __threadfence();
            float sum = 0.0f;
            for (int i = 0; i < CMB_BLKS; ++i) sum += g_partials[i];
            out[0] = sum * (1.0f / (float)TOTPTS);
            g_sync = 0;   // reset for next replay
        }
    }
}

extern "C" void kernel_launch(void* const* d_in, const int* in_sizes, int n_in,
                              void* d_out, int out_size)
{
    const float* centers = (const float*)d_in[0];
    float* out = (float*)d_out;

    nn_min_kernel<<<NBLK_MIN, TPB>>>(centers);
    nn_combine_final<<<CMB_BLKS, CMB_TPB>>>(out);
}

// round 10
// speedup vs baseline: 1.0643x; 1.0643x over previous
#include <cuda_runtime.h>
#include <math_constants.h>

// Problem constants (fixed: centers [8, 4096, 3] fp32)
#define BATCH    8
#define NPTS     4096
#define TOTPTS   (BATCH * NPTS)       // 32768
#define TPB      128                  // threads per block (min kernel)
#define IPT      4                    // i-points per thread
#define ITILE    (TPB * IPT)          // 512 i per block
#define NITILES  (NPTS / ITILE)       // 8
#define SSPLIT   64                   // j-splits
#define JT       (NPTS / SSPLIT)      // 64 j per block
#define NBLK_MIN (BATCH * NITILES * SSPLIT)   // 4096
#define FIN_BLKS 256
#define FIN_TPB  128
#define TARGET_F 0.2f

// Scratch (static device globals — no allocation allowed).
// g_key[point]: order-reversed monotone float key. key==0 decodes to the
// "+inf" sentinel, so the zero-initialized state IS the initialized state;
// the final kernel resets keys to 0 after reading (replay-safe).
__device__ unsigned int g_key[TOTPTS];           // 128 KB
__device__ float        g_partials[FIN_BLKS];
__device__ unsigned int g_sync;                  // zero-init; self-resets

// ---- order-reversed monotone float<->key (min via atomicMax) ----
__device__ __forceinline__ unsigned int f2key(float f) {
    unsigned int b = __float_as_uint(f);
    unsigned int mono = (b & 0x80000000u) ? ~b : (b | 0x80000000u);
    return ~mono;   // larger float -> smaller key; atomicMax keeps the min
}
__device__ __forceinline__ float key2f(unsigned int k) {
    unsigned int mono = ~k;
    unsigned int b = (mono & 0x80000000u) ? (mono ^ 0x80000000u) : ~mono;
    return __uint_as_float(b);
}

// ---- packed f32x2 helpers (FFMA2: only reachable via PTX) ----
__device__ __forceinline__ unsigned long long pack2(float a, float b) {
    unsigned long long r;
    asm("mov.b64 %0, {%1, %2};" : "=l"(r) : "f"(a), "f"(b));
    return r;
}
__device__ __forceinline__ unsigned long long fma2(unsigned long long a,
                                                   unsigned long long b,
                                                   unsigned long long c) {
    unsigned long long d;
    asm("fma.rn.f32x2 %0, %1, %2, %3;" : "=l"(d) : "l"(a), "l"(b), "l"(c));
    return d;
}
__device__ __forceinline__ float2 unpack2(unsigned long long v) {
    float2 f;
    asm("mov.b64 {%0, %1}, %2;" : "=f"(f.x), "=f"(f.y) : "l"(v));
    return f;
}

__global__ void __launch_bounds__(TPB)
nn_min_kernel(const float* __restrict__ centers)
{
    // SoA j-tile: LDS.128 per array yields pre-packed {j,j+1} f32x2 lanes
    __shared__ __align__(16) float spx[JT], spy[JT], spz[JT], spw[JT];

    const int blk = blockIdx.x;
    const int s   = blk & (SSPLIT - 1);            // j-split
    const int it  = (blk >> 6) & (NITILES - 1);    // i-tile
    const int b   = blk >> 9;                      // batch
    const int tid = threadIdx.x;

    const float* cb = centers + (size_t)b * NPTS * 3;
    const int j_lo  = s  * JT;
    const int i_lo  = it * ITILE;

    // Stage j-tile (64 points)
    for (int p = tid; p < JT; p += TPB) {
        float x = cb[3 * (j_lo + p) + 0];
        float y = cb[3 * (j_lo + p) + 1];
        float z = cb[3 * (j_lo + p) + 2];
        spx[p] = x; spy[p] = y; spz[p] = z;
        spw[p] = fmaf(x, x, fmaf(y, y, z * z));
    }

    // i-constants, pre-packed {c,c} once
    unsigned long long ax2[IPT], ay2[IPT], az2[IPT];
    float sqi[IPT], tminA[IPT], tminB[IPT];
    int   msel[IPT];   // local j index equal to this i (may be out of range)
    #pragma unroll
    for (int k = 0; k < IPT; ++k) {
        const int gi = i_lo + tid + k * TPB;
        float x = cb[3 * gi + 0];
        float y = cb[3 * gi + 1];
        float z = cb[3 * gi + 2];
        ax2[k] = pack2(-2.0f * x, -2.0f * x);
        ay2[k] = pack2(-2.0f * y, -2.0f * y);
        az2[k] = pack2(-2.0f * z, -2.0f * z);
        sqi[k] = fmaf(x, x, fmaf(y, y, z * z));
        tminA[k] = CUDART_INF_F;
        tminB[k] = CUDART_INF_F;
        msel[k] = gi - j_lo;
    }
    __syncthreads();

    const ulonglong2* px2 = (const ulonglong2*)spx;
    const ulonglong2* py2 = (const ulonglong2*)spy;
    const ulonglong2* pz2 = (const ulonglong2*)spz;
    const ulonglong2* pw2 = (const ulonglong2*)spw;

    if ((s >> 3) != it) {
        // Off-diagonal block: clean fully-unrolled loop, no compares
        #pragma unroll
        for (int q = 0; q < JT / 4; ++q) {
            const ulonglong2 px = px2[q], py = py2[q], pz = pz2[q], pw = pw2[q];
            #pragma unroll
            for (int k = 0; k < IPT; ++k) {
                unsigned long long t0 = fma2(pz.x, az2[k], pw.x);
                t0 = fma2(py.x, ay2[k], t0);
                t0 = fma2(px.x, ax2[k], t0);
                unsigned long long t1 = fma2(pz.y, az2[k], pw.y);
                t1 = fma2(py.y, ay2[k], t1);
                t1 = fma2(px.y, ax2[k], t1);
                float2 a = unpack2(t0), c = unpack2(t1);
                tminA[k] = fminf(tminA[k], fminf(a.x, a.y));
                tminB[k] = fminf(tminB[k], fminf(c.x, c.y));
            }
        }
    } else {
        // Diagonal block (1/8 of blocks): predicate out j == i
        #pragma unroll
        for (int q = 0; q < JT / 4; ++q) {
            const int jb = q * 4;
            const ulonglong2 px = px2[q], py = py2[q], pz = pz2[q], pw = pw2[q];
            #pragma unroll
            for (int k = 0; k < IPT; ++k) {
                unsigned long long t0 = fma2(pz.x, az2[k], pw.x);
                t0 = fma2(py.x, ay2[k], t0);
                t0 = fma2(px.x, ax2[k], t0);
                unsigned long long t1 = fma2(pz.y, az2[k], pw.y);
                t1 = fma2(py.y, ay2[k], t1);
                t1 = fma2(px.y, ax2[k], t1);
                float2 a = unpack2(t0), c = unpack2(t1);
                const int m = msel[k];
                a.x = (jb + 0 == m) ? CUDART_INF_F : a.x;
                a.y = (jb + 1 == m) ? CUDART_INF_F : a.y;
                c.x = (jb + 2 == m) ? CUDART_INF_F : c.x;
                c.y = (jb + 3 == m) ? CUDART_INF_F : c.y;
                tminA[k] = fminf(tminA[k], fminf(a.x, a.y));
                tminB[k] = fminf(tminB[k], fminf(c.x, c.y));
            }
        }
    }

    // Split-reduction via REDG.MAX on order-reversed keys (== float min).
    // Deterministic: min is associative/commutative, bit-exact any order.
    unsigned int* gk = g_key + b * NPTS + i_lo + tid;
    #pragma unroll
    for (int k = 0; k < IPT; ++k)
        atomicMax(&gk[k * TPB], f2key(sqi[k] + fminf(tminA[k], tminB[k])));
}

// Final: decode per-point min, loss, global mean (fused last-block-done).
// Also resets g_key to 0 so the graph replay (and next call) starts clean.
__global__ void __launch_bounds__(FIN_TPB)
nn_final_kernel(float* __restrict__ out)
{
    __shared__ float red[FIN_TPB];
    const int tid = threadIdx.x;
    const int pt  = blockIdx.x * FIN_TPB + tid;

    float m = key2f(g_key[pt]);
    g_key[pt] = 0u;                                  // reset for next replay
    float diff = sqrtf(fmaxf(m, 0.0f)) - TARGET_F;   // clamp like reference
    red[tid] = diff * diff;
    __syncthreads();
    #pragma unroll
    for (int st = FIN_TPB / 2; st > 0; st >>= 1) {
        if (tid < st) red[tid] += red[tid + st];
        __syncthreads();
    }
    if (tid == 0) {
        g_partials[blockIdx.x] = red[0];
        __threadfence();
        if (atomicAdd(&g_sync, 1u) == FIN_BLKS - 1) {
            __threadfence();
            float sum = 0.0f;
            for (int i = 0; i < FIN_BLKS; ++i) sum += g_partials[i];
            out[0] = sum * (1.0f / (float)TOTPTS);
            g_sync = 0;   // reset for next replay
        }
    }
}

extern "C" void kernel_launch(void* const* d_in, const int* in_sizes, int n_in,
                              void* d_out, int out_size)
{
    const float* centers = (const float*)d_in[0];
    float* out = (float*)d_out;

    nn_min_kernel<<<NBLK_MIN, TPB>>>(centers);
    nn_final_kernel<<<FIN_BLKS, FIN_TPB>>>(out);
}